// round 2
// baseline (speedup 1.0000x reference)
#include <cuda_runtime.h>

#define D 64
#define BATCHN 131072
#define SEQLEN 5
#define WARPS 16
#define R 4
#define TPB (WARPS * 32)
#define ROWS_PER_BLOCK (WARPS * R)
#define NBLOCKS (BATCHN / ROWS_PER_BLOCK)

// shared memory layout (float offsets)
#define OFF_W1N 0
#define OFF_W2N 4096
#define OFF_W1A 8192
#define OFF_W2A 16384
#define OFF_W1O 20480
#define OFF_W2O 28672
#define OFF_B   32768          // [not_b1,not_b2,and_b1,and_b2,or_b1,or_b2] = 6*64
#define OFF_TV  33152
#define OFF_STG 33216
#define STG_PER_WARP (4 * R * D)   // 4 buffers (b0,b1,b2,hidden) x R rows x 64
#define SMEM_FLOATS (OFF_STG + WARPS * STG_PER_WARP)
#define SMEM_BYTES  (SMEM_FLOATS * 4)

// Op table: x=kind(0 gather,1 mlp)
//  gather: y=src(0..4 seq pos, 5 pos_target, 6 neg_target), z=dst buf
//  mlp:    y=module(0 NOT,1 AND,2 OR), z=(in1<<3)|in2 (in2==7 -> none),
//          w=dst (0..2 buf, 4 write out[row], 5 write out[B+row])
__constant__ int4 OPS[16] = {
    {0, 1, 0, 0},              // gather e(seq1) -> b0
    {1, 0, (0 << 3) | 7, 1},   // n1 = NOT(b0) -> b1
    {0, 0, 0, 0},              // gather e(seq0) -> b0
    {1, 1, (0 << 3) | 1, 0},   // int5 = AND(b0,b1) -> b0
    {0, 2, 1, 0},              // gather e(seq2) -> b1
    {0, 3, 2, 0},              // gather e(seq3) -> b2
    {1, 2, (1 << 3) | 2, 1},   // int6 = OR(b1,b2) -> b1
    {1, 1, (0 << 3) | 1, 0},   // int7 = AND(b0,b1) -> b0
    {1, 0, (0 << 3) | 7, 1},   // n7 = NOT(b0) -> b1
    {0, 4, 2, 0},              // gather e(seq4) -> b2
    {1, 2, (1 << 3) | 2, 0},   // out = OR(b1,b2) -> b0
    {1, 0, (0 << 3) | 7, 0},   // enc_not = NOT(b0) -> b0
    {0, 5, 1, 0},              // gather pos_e -> b1
    {1, 2, (0 << 3) | 1, 4},   // ep = OR(b0,b1) -> write out[row]
    {0, 6, 1, 0},              // gather neg_e -> b1
    {1, 2, (0 << 3) | 1, 5}    // en = OR(b0,b1) -> write out[B+row]
};

__device__ __forceinline__ void cpy4(float* __restrict__ dst,
                                     const float* __restrict__ src, int n) {
    for (int i = threadIdx.x * 4; i < n; i += TPB * 4)
        *(float4*)(dst + i) = *(const float4*)(src + i);
}

// y[c0],y[c0+1] += x[R][64] @ W[64][64] for R rows simultaneously.
// W rows are LDS.64 per lane (conflict-free), x is LDS.128 broadcast.
__device__ __forceinline__ void matvec64(const float* __restrict__ W,
                                         const float* __restrict__ x,
                                         float a0[R], float a1[R], int c0) {
#pragma unroll
    for (int k = 0; k < D; k += 4) {
        float2 w0 = *(const float2*)(W + (k + 0) * D + c0);
        float2 w1 = *(const float2*)(W + (k + 1) * D + c0);
        float2 w2 = *(const float2*)(W + (k + 2) * D + c0);
        float2 w3 = *(const float2*)(W + (k + 3) * D + c0);
#pragma unroll
        for (int r = 0; r < R; r++) {
            float4 xv = *(const float4*)(x + r * D + k);
            a0[r] = fmaf(xv.x, w0.x, a0[r]); a1[r] = fmaf(xv.x, w0.y, a1[r]);
            a0[r] = fmaf(xv.y, w1.x, a0[r]); a1[r] = fmaf(xv.y, w1.y, a1[r]);
            a0[r] = fmaf(xv.z, w2.x, a0[r]); a1[r] = fmaf(xv.z, w2.y, a1[r]);
            a0[r] = fmaf(xv.w, w3.x, a0[r]); a1[r] = fmaf(xv.w, w3.y, a1[r]);
        }
    }
}

__global__ void __launch_bounds__(TPB, 1)
logicnet_kernel(const int* __restrict__ seq,
                const int* __restrict__ pos_t,
                const int* __restrict__ neg_t,
                const float* __restrict__ item_embed,
                const float* __restrict__ g_tv,
                const float* __restrict__ nW1, const float* __restrict__ nb1,
                const float* __restrict__ nW2, const float* __restrict__ nb2,
                const float* __restrict__ aW1, const float* __restrict__ ab1,
                const float* __restrict__ aW2, const float* __restrict__ ab2,
                const float* __restrict__ oW1, const float* __restrict__ ob1,
                const float* __restrict__ oW2, const float* __restrict__ ob2,
                float* __restrict__ out) {
    extern __shared__ float sm[];

    // ---- stage all weights/biases/true_vec into smem ----
    cpy4(sm + OFF_W1N, nW1, 4096);
    cpy4(sm + OFF_W2N, nW2, 4096);
    cpy4(sm + OFF_W1A, aW1, 8192);
    cpy4(sm + OFF_W2A, aW2, 4096);
    cpy4(sm + OFF_W1O, oW1, 8192);
    cpy4(sm + OFF_W2O, oW2, 4096);
    cpy4(sm + OFF_B +   0, nb1, 64);
    cpy4(sm + OFF_B +  64, nb2, 64);
    cpy4(sm + OFF_B + 128, ab1, 64);
    cpy4(sm + OFF_B + 192, ab2, 64);
    cpy4(sm + OFF_B + 256, ob1, 64);
    cpy4(sm + OFF_B + 320, ob2, 64);
    cpy4(sm + OFF_TV, g_tv, 64);
    __syncthreads();

    const int w    = threadIdx.x >> 5;
    const int lane = threadIdx.x & 31;
    const int c0   = lane * 2;
    const int grow = blockIdx.x * ROWS_PER_BLOCK + w * R;
    float* stg = sm + OFF_STG + w * STG_PER_WARP;
    const float* tv = sm + OFF_TV;

    // ||true_vec|| (warp reduce once)
    const float tv0 = tv[c0], tv1 = tv[c0 + 1];
    float t2 = fmaf(tv0, tv0, tv1 * tv1);
#pragma unroll
    for (int off = 16; off > 0; off >>= 1) t2 += __shfl_xor_sync(~0u, t2, off);
    const float tvd = fmaxf(sqrtf(t2), 1e-8f);

#pragma unroll 1
    for (int i = 0; i < 16; i++) {
        const int4 o = OPS[i];
        if (o.x == 0) {
            // ---- gather ----
            float* dst = stg + o.y * 0 + o.z * (R * D);
            __syncwarp();
#pragma unroll
            for (int r = 0; r < R; r++) {
                const int g = grow + r;
                int id;
                if (o.y < SEQLEN)      id = seq[g * SEQLEN + o.y];
                else if (o.y == 5)     id = pos_t[g];
                else                   id = neg_t[g];
                *(float2*)(dst + r * D + c0) =
                    *(const float2*)(item_embed + (size_t)id * D + c0);
            }
            __syncwarp();
        } else {
            // ---- MLP: leaky_relu(x@W1+b1)@W2+b2 ----
            const int mod = o.y;
            const float* W1 = sm + (mod == 0 ? OFF_W1N : mod == 1 ? OFF_W1A : OFF_W1O);
            const float* W2 = sm + (mod == 0 ? OFF_W2N : mod == 1 ? OFF_W2A : OFF_W2O);
            const float* b1 = sm + OFF_B + mod * 128;
            const float* b2 = b1 + D;
            const float* xA = stg + (o.z >> 3) * (R * D);
            const int in2 = o.z & 7;
            float* hb = stg + 3 * (R * D);

            float h0[R], h1[R];
            {
                const float bb0 = b1[c0], bb1 = b1[c0 + 1];
#pragma unroll
                for (int r = 0; r < R; r++) { h0[r] = bb0; h1[r] = bb1; }
            }
            matvec64(W1, xA, h0, h1, c0);
            if (in2 != 7) matvec64(W1 + D * D, stg + in2 * (R * D), h0, h1, c0);
            __syncwarp();
#pragma unroll
            for (int r = 0; r < R; r++) {
                const float v0 = h0[r] > 0.f ? h0[r] : 0.01f * h0[r];
                const float v1 = h1[r] > 0.f ? h1[r] : 0.01f * h1[r];
                *(float2*)(hb + r * D + c0) = make_float2(v0, v1);
            }
            __syncwarp();

            float a0[R], a1[R];
            {
                const float bb0 = b2[c0], bb1 = b2[c0 + 1];
#pragma unroll
                for (int r = 0; r < R; r++) { a0[r] = bb0; a1[r] = bb1; }
            }
            matvec64(W2, hb, a0, a1, c0);

            if (o.w < 4) {
                float* dst = stg + o.w * (R * D);
                __syncwarp();
#pragma unroll
                for (int r = 0; r < R; r++)
                    *(float2*)(dst + r * D + c0) = make_float2(a0[r], a1[r]);
                __syncwarp();
            } else {
                // cosine vs true_vec, scaled by 10
                float preds[R];
#pragma unroll
                for (int r = 0; r < R; r++) {
                    float nu = fmaf(a0[r], tv0, a1[r] * tv1);
                    float nr = fmaf(a0[r], a0[r], a1[r] * a1[r]);
#pragma unroll
                    for (int off = 16; off > 0; off >>= 1) {
                        nu += __shfl_xor_sync(~0u, nu, off);
                        nr += __shfl_xor_sync(~0u, nr, off);
                    }
                    preds[r] = nu / (fmaxf(sqrtf(nr), 1e-8f) * tvd) * 10.0f;
                }
                if (lane == 0) {
                    const int base = (o.w == 5 ? BATCHN : 0) + grow;
#pragma unroll
                    for (int r = 0; r < R; r++) out[base + r] = preds[r];
                }
            }
        }
    }
}

extern "C" void kernel_launch(void* const* d_in, const int* in_sizes, int n_in,
                              void* d_out, int out_size) {
    (void)in_sizes; (void)n_in; (void)out_size;
    cudaFuncSetAttribute(logicnet_kernel,
                         cudaFuncAttributeMaxDynamicSharedMemorySize, SMEM_BYTES);
    logicnet_kernel<<<NBLOCKS, TPB, SMEM_BYTES>>>(
        (const int*)d_in[0], (const int*)d_in[1], (const int*)d_in[2],
        (const float*)d_in[3], (const float*)d_in[4],
        (const float*)d_in[5], (const float*)d_in[6],
        (const float*)d_in[7], (const float*)d_in[8],
        (const float*)d_in[9], (const float*)d_in[10],
        (const float*)d_in[11], (const float*)d_in[12],
        (const float*)d_in[13], (const float*)d_in[14],
        (const float*)d_in[15], (const float*)d_in[16],
        (float*)d_out);
}

// round 3
// speedup vs baseline: 1.3770x; 1.3770x over previous
#include <cuda_runtime.h>

typedef unsigned long long u64;

#define D 64
#define BATCHN 131072
#define SEQLEN 5
#define WARPS 16
#define R 8                      // rows per warp (4 per half-warp)
#define TPB (WARPS * 32)
#define ROWS_PER_BLOCK (WARPS * R)
#define NBLOCKS (BATCHN / ROWS_PER_BLOCK)

// shared memory layout (float offsets)
#define OFF_W1N 0
#define OFF_W2N 4096
#define OFF_W1A 8192
#define OFF_W2A 16384
#define OFF_W1O 20480
#define OFF_W2O 28672
#define OFF_B   32768            // [not_b1,not_b2,and_b1,and_b2,or_b1,or_b2] 6*64
#define OFF_TV  33152
#define OFF_STG 33216
#define STG_PER_WARP (3 * R * D) // 3 buffers x 8 rows x 64
#define SMEM_FLOATS (OFF_STG + WARPS * STG_PER_WARP)
#define SMEM_BYTES  (SMEM_FLOATS * 4)

// Op table: x=kind(0 gather,1 mlp)
//  gather: y=src(0..4 seq pos, 5 pos_target, 6 neg_target), z=dst buf
//  mlp:    y=module(0 NOT,1 AND,2 OR),
//          z = in1 | (in2<<2) | (hid<<4)   (in2==3 -> single-input NOT)
//          w = out (0..2 buf, 4 -> out[row], 5 -> out[B+row])
__constant__ int4 OPS[16] = {
    {0, 1, 0, 0},                              // g e(seq1) -> b0
    {1, 0, 0 | (3 << 2) | (1 << 4), 0},        // n1 = NOT(b0) hid b1 -> b0
    {0, 0, 1, 0},                              // g e(seq0) -> b1
    {1, 1, 1 | (0 << 2) | (2 << 4), 0},        // int5 = AND(b1,b0) hid b2 -> b0
    {0, 2, 1, 0},                              // g e(seq2) -> b1
    {0, 3, 2, 0},                              // g e(seq3) -> b2
    {1, 2, 1 | (2 << 2) | (1 << 4), 1},        // int6 = OR(b1,b2) hid b1 -> b1
    {1, 1, 0 | (1 << 2) | (2 << 4), 0},        // int7 = AND(b0,b1) hid b2 -> b0
    {1, 0, 0 | (3 << 2) | (2 << 4), 0},        // n7 = NOT(b0) hid b2 -> b0
    {0, 4, 1, 0},                              // g e(seq4) -> b1
    {1, 2, 0 | (1 << 2) | (2 << 4), 0},        // out = OR(b0,b1) hid b2 -> b0
    {1, 0, 0 | (3 << 2) | (1 << 4), 0},        // enc_not = NOT(b0) hid b1 -> b0
    {0, 5, 1, 0},                              // g pos_e -> b1
    {1, 2, 0 | (1 << 2) | (2 << 4), 4},        // OR(b0,b1) -> out[row]
    {0, 6, 1, 0},                              // g neg_e -> b1
    {1, 2, 0 | (1 << 2) | (2 << 4), 5}         // OR(b0,b1) -> out[B+row]
};

__device__ __forceinline__ u64 dup2(float a) {
    u64 r; asm("mov.b64 %0, {%1,%1};" : "=l"(r) : "f"(a)); return r;
}
__device__ __forceinline__ void unpk(float& lo, float& hi, u64 p) {
    asm("mov.b64 {%0,%1}, %2;" : "=f"(lo), "=f"(hi) : "l"(p));
}
__device__ __forceinline__ void ffma2(u64& d, u64 a, u64 b) {
    asm("fma.rn.f32x2 %0, %1, %2, %0;" : "+l"(d) : "l"(a), "l"(b));
}

__device__ __forceinline__ void cpy4(float* __restrict__ dst,
                                     const float* __restrict__ src, int n) {
    for (int i = threadIdx.x * 4; i < n; i += TPB * 4)
        *(float4*)(dst + i) = *(const float4*)(src + i);
}

// accA[rl] = cols {c0,c0+1}, accB[rl] = cols {c0+2,c0+3} of rows h*4+rl.
// W row-major [64][64] in smem; x = staging buffer [8][64].
__device__ __forceinline__ void mv(const float* __restrict__ W,
                                   const float* __restrict__ x,
                                   u64 accA[4], u64 accB[4], int c0, int h) {
#pragma unroll 8
    for (int k = 0; k < D; k += 4) {
        ulonglong2 w0 = *(const ulonglong2*)(W + (k + 0) * D + c0);
        ulonglong2 w1 = *(const ulonglong2*)(W + (k + 1) * D + c0);
        ulonglong2 w2 = *(const ulonglong2*)(W + (k + 2) * D + c0);
        ulonglong2 w3 = *(const ulonglong2*)(W + (k + 3) * D + c0);
#pragma unroll
        for (int rl = 0; rl < 4; rl++) {
            float4 xv = *(const float4*)(x + (h * 4 + rl) * D + k);
            u64 xx;
            xx = dup2(xv.x); ffma2(accA[rl], xx, w0.x); ffma2(accB[rl], xx, w0.y);
            xx = dup2(xv.y); ffma2(accA[rl], xx, w1.x); ffma2(accB[rl], xx, w1.y);
            xx = dup2(xv.z); ffma2(accA[rl], xx, w2.x); ffma2(accB[rl], xx, w2.y);
            xx = dup2(xv.w); ffma2(accA[rl], xx, w3.x); ffma2(accB[rl], xx, w3.y);
        }
    }
}

__device__ __forceinline__ float lrelu(float v) {
    return fmaxf(v, 0.f) + 0.01f * fminf(v, 0.f);
}

__global__ void __launch_bounds__(TPB, 1)
logicnet_kernel(const int* __restrict__ seq,
                const int* __restrict__ pos_t,
                const int* __restrict__ neg_t,
                const float* __restrict__ item_embed,
                const float* __restrict__ g_tv,
                const float* __restrict__ nW1, const float* __restrict__ nb1,
                const float* __restrict__ nW2, const float* __restrict__ nb2,
                const float* __restrict__ aW1, const float* __restrict__ ab1,
                const float* __restrict__ aW2, const float* __restrict__ ab2,
                const float* __restrict__ oW1, const float* __restrict__ ob1,
                const float* __restrict__ oW2, const float* __restrict__ ob2,
                float* __restrict__ out) {
    extern __shared__ float sm[];

    // ---- stage weights/biases/true_vec ----
    cpy4(sm + OFF_W1N, nW1, 4096);
    cpy4(sm + OFF_W2N, nW2, 4096);
    cpy4(sm + OFF_W1A, aW1, 8192);
    cpy4(sm + OFF_W2A, aW2, 4096);
    cpy4(sm + OFF_W1O, oW1, 8192);
    cpy4(sm + OFF_W2O, oW2, 4096);
    cpy4(sm + OFF_B +   0, nb1, 64);
    cpy4(sm + OFF_B +  64, nb2, 64);
    cpy4(sm + OFF_B + 128, ab1, 64);
    cpy4(sm + OFF_B + 192, ab2, 64);
    cpy4(sm + OFF_B + 256, ob1, 64);
    cpy4(sm + OFF_B + 320, ob2, 64);
    cpy4(sm + OFF_TV, g_tv, 64);
    __syncthreads();

    const int w    = threadIdx.x >> 5;
    const int lane = threadIdx.x & 31;
    const int h    = lane >> 4;        // half-warp: row group
    const int lq   = lane & 15;        // column group
    const int c0   = lq * 4;
    const int rbase = blockIdx.x * ROWS_PER_BLOCK + w * R + h * 4; // row of rl=0
    float* stg = sm + OFF_STG + w * STG_PER_WARP;

    // true_vec: this lane's 4 cols + norm (reduce within 16-lane half)
    const float4 tvv = *(const float4*)(sm + OFF_TV + c0);
    float t2 = tvv.x * tvv.x + tvv.y * tvv.y + tvv.z * tvv.z + tvv.w * tvv.w;
#pragma unroll
    for (int off = 8; off > 0; off >>= 1) t2 += __shfl_xor_sync(~0u, t2, off);
    const float tvd = fmaxf(sqrtf(t2), 1e-8f);

#pragma unroll 1
    for (int i = 0; i < 16; i++) {
        const int4 o = OPS[i];
        if (o.x == 0) {
            // ---- gather 4 rows x 4 cols ----
            float* dst = stg + o.z * (R * D);
            __syncwarp();
#pragma unroll
            for (int rl = 0; rl < 4; rl++) {
                const int g = rbase + rl;
                int id;
                if (o.y < SEQLEN)  id = seq[g * SEQLEN + o.y];
                else if (o.y == 5) id = pos_t[g];
                else               id = neg_t[g];
                *(float4*)(dst + (h * 4 + rl) * D + c0) =
                    *(const float4*)(item_embed + (size_t)id * D + c0);
            }
            __syncwarp();
        } else {
            // ---- MLP: leaky_relu(x@W1+b1)@W2+b2 ----
            const int mod = o.y;
            const float* W1 = sm + (mod == 0 ? OFF_W1N : mod == 1 ? OFF_W1A : OFF_W1O);
            const float* W2 = sm + (mod == 0 ? OFF_W2N : mod == 1 ? OFF_W2A : OFF_W2O);
            const float* b1 = sm + OFF_B + mod * 128;
            const float* b2 = b1 + D;
            const int in1 = o.z & 3, in2 = (o.z >> 2) & 3, hid = (o.z >> 4) & 3;
            float* hb = stg + hid * (R * D);

            u64 hA[4], hB[4];
            {
                ulonglong2 bp = *(const ulonglong2*)(b1 + c0);
#pragma unroll
                for (int rl = 0; rl < 4; rl++) { hA[rl] = bp.x; hB[rl] = bp.y; }
            }
            mv(W1, stg + in1 * (R * D), hA, hB, c0, h);
            if (in2 != 3) mv(W1 + D * D, stg + in2 * (R * D), hA, hB, c0, h);
            __syncwarp();
#pragma unroll
            for (int rl = 0; rl < 4; rl++) {
                float v0, v1, v2, v3;
                unpk(v0, v1, hA[rl]); unpk(v2, v3, hB[rl]);
                *(float4*)(hb + (h * 4 + rl) * D + c0) =
                    make_float4(lrelu(v0), lrelu(v1), lrelu(v2), lrelu(v3));
            }
            __syncwarp();

            u64 aA[4], aB[4];
            {
                ulonglong2 bp = *(const ulonglong2*)(b2 + c0);
#pragma unroll
                for (int rl = 0; rl < 4; rl++) { aA[rl] = bp.x; aB[rl] = bp.y; }
            }
            mv(W2, hb, aA, aB, c0, h);
            __syncwarp();

            if (o.w < 4) {
                float* dst = stg + o.w * (R * D);
#pragma unroll
                for (int rl = 0; rl < 4; rl++) {
                    float v0, v1, v2, v3;
                    unpk(v0, v1, aA[rl]); unpk(v2, v3, aB[rl]);
                    *(float4*)(dst + (h * 4 + rl) * D + c0) =
                        make_float4(v0, v1, v2, v3);
                }
                __syncwarp();
            } else {
                // cosine vs true_vec, x10
                float preds[4];
#pragma unroll
                for (int rl = 0; rl < 4; rl++) {
                    float v0, v1, v2, v3;
                    unpk(v0, v1, aA[rl]); unpk(v2, v3, aB[rl]);
                    float nu = v0 * tvv.x + v1 * tvv.y + v2 * tvv.z + v3 * tvv.w;
                    float nr = v0 * v0 + v1 * v1 + v2 * v2 + v3 * v3;
#pragma unroll
                    for (int off = 8; off > 0; off >>= 1) {
                        nu += __shfl_xor_sync(~0u, nu, off);
                        nr += __shfl_xor_sync(~0u, nr, off);
                    }
                    preds[rl] = nu / (fmaxf(sqrtf(nr), 1e-8f) * tvd) * 10.0f;
                }
                if (lq == 0) {
                    const int base = (o.w == 5 ? BATCHN : 0) + rbase;
#pragma unroll
                    for (int rl = 0; rl < 4; rl++) out[base + rl] = preds[rl];
                }
            }
        }
    }
}

extern "C" void kernel_launch(void* const* d_in, const int* in_sizes, int n_in,
                              void* d_out, int out_size) {
    (void)in_sizes; (void)n_in; (void)out_size;
    cudaFuncSetAttribute(logicnet_kernel,
                         cudaFuncAttributeMaxDynamicSharedMemorySize, SMEM_BYTES);
    logicnet_kernel<<<NBLOCKS, TPB, SMEM_BYTES>>>(
        (const int*)d_in[0], (const int*)d_in[1], (const int*)d_in[2],
        (const float*)d_in[3], (const float*)d_in[4],
        (const float*)d_in[5], (const float*)d_in[6],
        (const float*)d_in[7], (const float*)d_in[8],
        (const float*)d_in[9], (const float*)d_in[10],
        (const float*)d_in[11], (const float*)d_in[12],
        (const float*)d_in[13], (const float*)d_in[14],
        (const float*)d_in[15], (const float*)d_in[16],
        (float*)d_out);
}